// round 14
// baseline (speedup 1.0000x reference)
#include <cuda_runtime.h>
#include <cuda_fp16.h>
#include <math.h>

#define BATCH 4
#define SEQ   2048
#define DM    1024
#define NH    16
#define HD    64
#define MROWS (BATCH * SEQ)   // 8192

__device__ __half g_qkv[3][BATCH * NH * SEQ * HD];
__device__ __half g_ctx[MROWS * DM];
__device__ __half g_xh[MROWS * DM];
__device__ __half g_wth[4][DM * DM];       // fp16 TRANSPOSED weights [out][in]

// ---------------------------------------------------------------------------
// helpers
// ---------------------------------------------------------------------------
__device__ __forceinline__ unsigned h2pack(float a, float b) {
    __half2 h = __floats2half2_rn(a, b);
    return *(unsigned*)&h;
}

__device__ __forceinline__ void mma_fp16(float* d, const unsigned* a,
                                         unsigned b0, unsigned b1) {
    asm volatile(
        "mma.sync.aligned.m16n8k16.row.col.f32.f16.f16.f32 "
        "{%0,%1,%2,%3}, {%4,%5,%6,%7}, {%8,%9}, {%0,%1,%2,%3};\n"
        : "+f"(d[0]), "+f"(d[1]), "+f"(d[2]), "+f"(d[3])
        : "r"(a[0]), "r"(a[1]), "r"(a[2]), "r"(a[3]), "r"(b0), "r"(b1));
}

__device__ __forceinline__ unsigned ex2_f16x2(unsigned x) {
    unsigned r;
    asm("ex2.approx.f16x2 %0, %1;" : "=r"(r) : "r"(x));
    return r;
}

__device__ __forceinline__ unsigned saddr(const void* p) {
    return (unsigned)__cvta_generic_to_shared(p);
}
__device__ __forceinline__ void cp16(unsigned d, const void* s) {
    asm volatile("cp.async.cg.shared.global [%0], [%1], 16;" :: "r"(d), "l"(s));
}
#define CP_COMMIT asm volatile("cp.async.commit_group;")
#define CP_WAIT0  asm volatile("cp.async.wait_group 0;")
#define CP_WAIT1  asm volatile("cp.async.wait_group 1;")

__device__ __forceinline__ void ldsm4(unsigned& r0, unsigned& r1,
                                      unsigned& r2, unsigned& r3, unsigned a) {
    asm volatile("ldmatrix.sync.aligned.m8n8.x4.shared.b16 {%0,%1,%2,%3}, [%4];"
                 : "=r"(r0), "=r"(r1), "=r"(r2), "=r"(r3) : "r"(a));
}
__device__ __forceinline__ void ldsm4t(unsigned& r0, unsigned& r1,
                                       unsigned& r2, unsigned& r3, unsigned a) {
    asm volatile("ldmatrix.sync.aligned.m8n8.x4.trans.shared.b16 {%0,%1,%2,%3}, [%4];"
                 : "=r"(r0), "=r"(r1), "=r"(r2), "=r"(r3) : "r"(a));
}

// ---------------------------------------------------------------------------
// preprocessing
// ---------------------------------------------------------------------------
__global__ void round_fp16_k(const float* __restrict__ in,
                             __half* __restrict__ out, int n4)
{
    int i = blockIdx.x * blockDim.x + threadIdx.x;
    if (i < n4) {
        float4 v = ((const float4*)in)[i];
        __half2* o = (__half2*)(out + i * 4);
        o[0] = __floats2half2_rn(v.x, v.y);
        o[1] = __floats2half2_rn(v.z, v.w);
    }
}

__global__ void transpose_fp16_k(const float* __restrict__ w0,
                                 const float* __restrict__ w1,
                                 const float* __restrict__ w2,
                                 const float* __restrict__ w3,
                                 __half* __restrict__ out)
{
    __shared__ float t[32][33];
    const float* in = (blockIdx.z == 0) ? w0 : (blockIdx.z == 1) ? w1
                    : (blockIdx.z == 2) ? w2 : w3;
    __half* o = out + (size_t)blockIdx.z * DM * DM;
    int bx = blockIdx.x * 32, by = blockIdx.y * 32;
    int tx = threadIdx.x;
#pragma unroll
    for (int i = threadIdx.y; i < 32; i += 8)
        t[i][tx] = in[(size_t)(by + i) * DM + bx + tx];
    __syncthreads();
#pragma unroll
    for (int i = threadIdx.y; i < 32; i += 8)
        o[(size_t)(bx + i) * DM + by + tx] = __float2half_rn(t[tx][i]);
}

// ---------------------------------------------------------------------------
// fp16 GEMM core: CTA tile 256x128, 512 threads, 16 warps (4M x 4N),
// warp tile 64x32, BK=64 halves, 3-stage cp.async ring, m16n8k16.
// ---------------------------------------------------------------------------
#define G_STR 72
#define GA_TILE_B (256 * G_STR * 2)       // 36864 B
#define GB_TILE_B (128 * G_STR * 2)       // 18432 B
#define G_STAGE_B (GA_TILE_B + GB_TILE_B) // 55296 B
#define G_SMEM (3 * G_STAGE_B)            // 165888 B

__device__ __forceinline__ void gemm_stage(
    const __half* __restrict__ A, const __half* __restrict__ Bt,
    unsigned stageBase, int rowBase, int colBase, int k0, int tid)
{
    unsigned Ab = stageBase;
    unsigned Bb = stageBase + GA_TILE_B;
#pragma unroll
    for (int it = 0; it < 4; it++) {      // A: 256 rows x 8 cp16
        int idx = tid + it * 512;         // 0..2047
        int r   = idx >> 3;               // 0..255
        int c8  = (idx & 7) * 8;
        cp16(Ab + (unsigned)(r * G_STR + c8) * 2,
             A  + (size_t)(rowBase + r) * DM + k0 + c8);
    }
#pragma unroll
    for (int it = 0; it < 2; it++) {      // B: 128 rows x 8 cp16
        int idx = tid + it * 512;         // 0..1023
        int r   = idx >> 3;               // 0..127
        int c8  = (idx & 7) * 8;
        cp16(Bb + (unsigned)(r * G_STR + c8) * 2,
             Bt + (size_t)(colBase + r) * DM + k0 + c8);
    }
}

struct GemmOut {
    float d[4][4][4];     // 4 m-frags x 4 n-frags
};

__device__ __forceinline__ void gemm_core(
    const __half* A, const __half* Bt, unsigned s0,
    int rowBase, int colBase, int tid, int lane, int warpM, int warpN,
    GemmOut& o)
{
#pragma unroll
    for (int mf = 0; mf < 4; mf++)
#pragma unroll
        for (int nt = 0; nt < 4; nt++)
#pragma unroll
            for (int j = 0; j < 4; j++) o.d[mf][nt][j] = 0.f;

    const unsigned aOff =
        ((unsigned)((warpM * 64 + (lane & 15)) * G_STR + (lane >> 4) * 8)) * 2u;
    const unsigned bOff = GA_TILE_B +
        ((unsigned)((warpN * 32 + (lane & 7) + ((lane >> 4) & 1) * 8) * G_STR
                    + ((lane >> 3) & 1) * 8)) * 2u;

    gemm_stage(A, Bt, s0,             rowBase, colBase, 0,  tid); CP_COMMIT;
    gemm_stage(A, Bt, s0 + G_STAGE_B, rowBase, colBase, 64, tid); CP_COMMIT;

    for (int itn = 0; itn < 16; itn++) {
        const unsigned stg = s0 + (unsigned)(itn % 3) * G_STAGE_B;
        if (itn >= 14) { CP_WAIT0; } else { CP_WAIT1; }
        __syncthreads();
        if (itn + 2 < 16) {
            gemm_stage(A, Bt, s0 + (unsigned)((itn + 2) % 3) * G_STAGE_B,
                       rowBase, colBase, (itn + 2) * 64, tid);
            CP_COMMIT;
        }
        const unsigned aB = stg + aOff;
        const unsigned bB = stg + bOff;

#pragma unroll
        for (int kk = 0; kk < 4; kk++) {     // 4 x k16
            unsigned a[4][4];
#pragma unroll
            for (int mf = 0; mf < 4; mf++)
                ldsm4(a[mf][0], a[mf][1], a[mf][2], a[mf][3],
                      aB + mf * 16 * G_STR * 2 + kk * 32);
#pragma unroll
            for (int p = 0; p < 2; p++) {    // 2 ldsm -> 4 n-frags
                unsigned r0, r1, r2, r3;
                ldsm4(r0, r1, r2, r3, bB + p * 16 * G_STR * 2 + kk * 32);
#pragma unroll
                for (int mf = 0; mf < 4; mf++) {
                    mma_fp16(o.d[mf][2 * p],     a[mf], r0, r1);
                    mma_fp16(o.d[mf][2 * p + 1], a[mf], r2, r3);
                }
            }
        }
    }
}

// QKV GEMM: grid.z selects q/k/v; scatter fp16 to [b,h,s,hd]
__global__ __launch_bounds__(512, 1) void gemm_qkv(
    const __half* __restrict__ A, const __half* __restrict__ WtBase,
    const float* __restrict__ bq, const float* __restrict__ bk,
    const float* __restrict__ bv, __half* __restrict__ Obase)
{
    extern __shared__ __half gsm[];
    const unsigned s0 = saddr(gsm);

    const int z = blockIdx.z;
    const __half* Bt = WtBase + (size_t)z * DM * DM;
    const float* bias = (z == 0) ? bq : (z == 1) ? bk : bv;
    __half* C = Obase + (size_t)z * (BATCH * NH * SEQ * HD);
    const float scale = (z == 0) ? 0.125f * 1.4426950408889634f : 1.0f;

    const int tid   = threadIdx.x;
    const int lane  = tid & 31;
    const int warp  = tid >> 5;
    const int warpM = warp & 3;
    const int warpN = warp >> 2;
    const int g     = lane >> 2;
    const int t     = lane & 3;
    const int rowBase = blockIdx.y * 256;
    const int colBase = blockIdx.x * 128;

    GemmOut o;
    gemm_core(A, Bt, s0, rowBase, colBase, tid, lane, warpM, warpN, o);

#pragma unroll
    for (int mf = 0; mf < 4; mf++) {
        int row0 = rowBase + warpM * 64 + mf * 16 + g;
#pragma unroll
        for (int nt = 0; nt < 4; nt++) {
            int col = colBase + warpN * 32 + nt * 8 + 2 * t;
            float bb0 = bias[col], bb1 = bias[col + 1];
            unsigned v0 = h2pack((o.d[mf][nt][0] + bb0) * scale,
                                 (o.d[mf][nt][1] + bb1) * scale);
            unsigned v1 = h2pack((o.d[mf][nt][2] + bb0) * scale,
                                 (o.d[mf][nt][3] + bb1) * scale);
            int h = col >> 6, hd = col & 63;
            int b0i = row0 >> 11, s0i = row0 & 2047;
            int r1 = row0 + 8;
            int b1i = r1 >> 11, s1i = r1 & 2047;
            *(unsigned*)(C + (((size_t)(b0i * NH + h) * SEQ) + s0i) * HD + hd) = v0;
            *(unsigned*)(C + (((size_t)(b1i * NH + h) * SEQ) + s1i) * HD + hd) = v1;
        }
    }
}

// Output GEMM: fp32 plain row-major out
__global__ __launch_bounds__(512, 1) void gemm_out(
    const __half* __restrict__ A, const __half* __restrict__ Bt,
    const float* __restrict__ bias, float* __restrict__ C)
{
    extern __shared__ __half gsm[];
    const unsigned s0 = saddr(gsm);

    const int tid   = threadIdx.x;
    const int lane  = tid & 31;
    const int warp  = tid >> 5;
    const int warpM = warp & 3;
    const int warpN = warp >> 2;
    const int g     = lane >> 2;
    const int t     = lane & 3;
    const int rowBase = blockIdx.y * 256;
    const int colBase = blockIdx.x * 128;

    GemmOut o;
    gemm_core(A, Bt, s0, rowBase, colBase, tid, lane, warpM, warpN, o);

#pragma unroll
    for (int mf = 0; mf < 4; mf++) {
        int row0 = rowBase + warpM * 64 + mf * 16 + g;
#pragma unroll
        for (int nt = 0; nt < 4; nt++) {
            int col = colBase + warpN * 32 + nt * 8 + 2 * t;
            float bb0 = bias[col], bb1 = bias[col + 1];
            *(float2*)(C + (size_t)row0 * DM + col) =
                make_float2(o.d[mf][nt][0] + bb0, o.d[mf][nt][1] + bb1);
            *(float2*)(C + (size_t)(row0 + 8) * DM + col) =
                make_float2(o.d[mf][nt][2] + bb0, o.d[mf][nt][3] + bb1);
        }
    }
}

// ---------------------------------------------------------------------------
// Flash attention fp16 (unchanged from R11): 64q x 64k, 128 threads,
// 4 CTAs/SM, ex2.f16x2 softmax, row-sum l via all-ones MMA column.
// ---------------------------------------------------------------------------
#define F_STR 72
#define FQ_B (64 * F_STR * 2)
#define FK_B (64 * F_STR * 2)
#define FA_SMEM (FQ_B + 4 * FK_B)  // 46080

#define ONES_H2 0x3C003C00u

__device__ __forceinline__ void fa_stage(
    const __half* __restrict__ Kb, const __half* __restrict__ Vb,
    unsigned Kd, unsigned Vd, int tid)
{
#pragma unroll
    for (int it = 0; it < 4; it++) {
        int idx = tid + it * 128;
        int r   = idx >> 3;
        int c8  = (idx & 7) * 8;
        cp16(Kd + (unsigned)(r * F_STR + c8) * 2, Kb + r * HD + c8);
        cp16(Vd + (unsigned)(r * F_STR + c8) * 2, Vb + r * HD + c8);
    }
}

__global__ __launch_bounds__(128, 4) void flash_fp16(
    const __half* __restrict__ Q, const __half* __restrict__ K,
    const __half* __restrict__ V, __half* __restrict__ ctx)
{
    extern __shared__ __half fsm[];
    const unsigned sQ = saddr(fsm);
    const unsigned sK = sQ + FQ_B;
    const unsigned sV = sK + 2 * FK_B;

    const int tid  = threadIdx.x;
    const int lane = tid & 31;
    const int warp = tid >> 5;
    const int g    = lane >> 2;
    const int t    = lane & 3;
    const int qt   = blockIdx.x;
    const int bh   = blockIdx.y;
    const int Q0   = qt * 64;
    const int rb   = warp * 16;

    const size_t base = (size_t)bh * SEQ * HD;

    const unsigned qAddr = sQ +
        ((unsigned)((rb + (lane & 15)) * F_STR + (lane >> 4) * 8)) * 2u;
    const unsigned kOff =
        ((unsigned)(((lane & 7) + ((lane >> 4) & 1) * 8) * F_STR
                    + ((lane >> 3) & 1) * 8)) * 2u;
    const unsigned vOff =
        ((unsigned)(((lane & 7) + ((lane >> 3) & 1) * 8) * F_STR
                    + (lane >> 4) * 8)) * 2u;

    {
        const __half* Qb = Q + base + (size_t)Q0 * HD;
#pragma unroll
        for (int it = 0; it < 4; it++) {
            int idx = tid + it * 128;
            int r   = idx >> 3;
            int c8  = (idx & 7) * 8;
            cp16(sQ + (unsigned)(r * F_STR + c8) * 2, Qb + r * HD + c8);
        }
        fa_stage(K + base, V + base, sK, sV, tid);
        CP_COMMIT;
    }

    float m[2] = {-INFINITY, -INFINITY};
    float O[9][4];
#pragma unroll
    for (int nf = 0; nf < 9; nf++)
#pragma unroll
        for (int j = 0; j < 4; j++) O[nf][j] = 0.f;

    int buf = 0;
    for (int kt = 0; kt <= qt; kt++) {
        CP_WAIT0;
        __syncthreads();
        if (kt < qt) {
            fa_stage(K + base + (size_t)(kt + 1) * 64 * HD,
                     V + base + (size_t)(kt + 1) * 64 * HD,
                     sK + (buf ^ 1) * FK_B, sV + (buf ^ 1) * FK_B, tid);
            CP_COMMIT;
        }
        const unsigned kB = sK + buf * FK_B + kOff;
        const unsigned vB = sV + buf * FK_B + vOff;

        float S[8][4];
#pragma unroll
        for (int nf = 0; nf < 8; nf++)
#pragma unroll
            for (int j = 0; j < 4; j++) S[nf][j] = 0.f;

#pragma unroll
        for (int kk = 0; kk < 4; kk++) {
            unsigned a[4];
            ldsm4(a[0], a[1], a[2], a[3], qAddr + kk * 32);
#pragma unroll
            for (int p = 0; p < 4; p++) {
                unsigned r0, r1, r2, r3;
                ldsm4(r0, r1, r2, r3, kB + p * 16 * F_STR * 2 + kk * 32);
                mma_fp16(S[2 * p],     a, r0, r1);
                mma_fp16(S[2 * p + 1], a, r2, r3);
            }
        }

        if (kt == qt) {
            int kb = kt * 64;
            int rlo = Q0 + rb + g, rhi = rlo + 8;
#pragma unroll
            for (int nf = 0; nf < 8; nf++) {
                int k0 = kb + nf * 8 + 2 * t;
                if (k0     > rlo) S[nf][0] = -INFINITY;
                if (k0 + 1 > rlo) S[nf][1] = -INFINITY;
                if (k0     > rhi) S[nf][2] = -INFINITY;
                if (k0 + 1 > rhi) S[nf][3] = -INFINITY;
            }
        }

        float sc0, sc1;
        {
            float mx0 = -INFINITY, mx1 = -INFINITY;
#pragma unroll
            for (int nf = 0; nf < 8; nf++) {
                mx0 = fmaxf(mx0, fmaxf(S[nf][0], S[nf][1]));
                mx1 = fmaxf(mx1, fmaxf(S[nf][2], S[nf][3]));
            }
            mx0 = fmaxf(mx0, __shfl_xor_sync(0xffffffffu, mx0, 1));
            mx0 = fmaxf(mx0, __shfl_xor_sync(0xffffffffu, mx0, 2));
            mx1 = fmaxf(mx1, __shfl_xor_sync(0xffffffffu, mx1, 1));
            mx1 = fmaxf(mx1, __shfl_xor_sync(0xffffffffu, mx1, 2));
            float mn0 = fmaxf(m[0], mx0);
            float mn1 = fmaxf(m[1], mx1);
            sc0 = exp2f(m[0] - mn0);
            sc1 = exp2f(m[1] - mn1);
            m[0] = mn0; m[1] = mn1;
        }

        unsigned E[8][2];
        {
            __half2 hm0 = __float2half2_rn(m[0]);
            __half2 hm1 = __float2half2_rn(m[1]);
#pragma unroll
            for (int nf = 0; nf < 8; nf++) {
                __half2 p0 = __floats2half2_rn(S[nf][0], S[nf][1]);
                __half2 p1 = __floats2half2_rn(S[nf][2], S[nf][3]);
                p0 = __hsub2(p0, hm0);
                p1 = __hsub2(p1, hm1);
                E[nf][0] = ex2_f16x2(*(unsigned*)&p0);
                E[nf][1] = ex2_f16x2(*(unsigned*)&p1);
            }
        }

#pragma unroll
        for (int nf = 0; nf < 9; nf++) {
            O[nf][0] *= sc0; O[nf][1] *= sc0;
            O[nf][2] *= sc1; O[nf][3] *= sc1;
        }

#pragma unroll
        for (int mkey = 0; mkey < 4; mkey++) {
            unsigned a[4];
            a[0] = E[2 * mkey][0];
            a[1] = E[2 * mkey][1];
            a[2] = E[2 * mkey + 1][0];
            a[3] = E[2 * mkey + 1][1];
#pragma unroll
            for (int p = 0; p < 4; p++) {
                unsigned r0, r1, r2, r3;
                ldsm4t(r0, r1, r2, r3,
                       vB + (mkey * 16 * F_STR + p * 16) * 2);
                mma_fp16(O[2 * p],     a, r0, r1);
                mma_fp16(O[2 * p + 1], a, r2, r3);
            }
            mma_fp16(O[8], a, ONES_H2, ONES_H2);
        }
        buf ^= 1;
    }

    const int b = bh >> 4, hh = bh & 15;
    const float inv0 = 1.f / O[8][0];
    const float inv1 = 1.f / O[8][2];
#pragma unroll
    for (int h2 = 0; h2 < 2; h2++) {
        float inv = h2 ? inv1 : inv0;
        int row = Q0 + rb + g + 8 * h2;
        __half* dst = ctx + ((size_t)(b * SEQ + row)) * DM + hh * HD;
#pragma unroll
        for (int nf = 0; nf < 8; nf++) {
            int c = nf * 8 + 2 * t;
            *(unsigned*)(dst + c) =
                h2pack(O[nf][2 * h2] * inv, O[nf][2 * h2 + 1] * inv);
        }
    }
}

// ---------------------------------------------------------------------------
// Launch
// ---------------------------------------------------------------------------
extern "C" void kernel_launch(void* const* d_in, const int* in_sizes, int n_in,
                              void* d_out, int out_size)
{
    const float* x  = (const float*)d_in[0];
    const float* wq = (const float*)d_in[1];
    const float* bq = (const float*)d_in[2];
    const float* wk = (const float*)d_in[3];
    const float* bk = (const float*)d_in[4];
    const float* wv = (const float*)d_in[5];
    const float* bv = (const float*)d_in[6];
    const float* wo = (const float*)d_in[7];
    const float* bo = (const float*)d_in[8];
    float* out = (float*)d_out;

    __half *qkv, *ctx, *xh, *wth;
    cudaGetSymbolAddress((void**)&qkv, g_qkv);
    cudaGetSymbolAddress((void**)&ctx, g_ctx);
    cudaGetSymbolAddress((void**)&xh,  g_xh);
    cudaGetSymbolAddress((void**)&wth, g_wth);
    const size_t HSZ = (size_t)BATCH * NH * SEQ * HD;

    cudaFuncSetAttribute(gemm_qkv,
                         cudaFuncAttributeMaxDynamicSharedMemorySize, G_SMEM);
    cudaFuncSetAttribute(gemm_out,
                         cudaFuncAttributeMaxDynamicSharedMemorySize, G_SMEM);
    cudaFuncSetAttribute(flash_fp16,
                         cudaFuncAttributeMaxDynamicSharedMemorySize, FA_SMEM);

    {
        int n4x = MROWS * DM / 4;
        round_fp16_k<<<(n4x + 255) / 256, 256>>>(x, xh, n4x);
        transpose_fp16_k<<<dim3(32, 32, 4), dim3(32, 8)>>>(wq, wk, wv, wo, wth);
    }

    gemm_qkv<<<dim3(DM / 128, MROWS / 256, 3), 512, G_SMEM>>>(
        xh, wth, bq, bk, bv, qkv);

    flash_fp16<<<dim3(SEQ / 64, BATCH * NH), 128, FA_SMEM>>>(
        qkv, qkv + HSZ, qkv + 2 * HSZ, ctx);

    gemm_out<<<dim3(DM / 128, MROWS / 256), 512, G_SMEM>>>(
        ctx, wth + 3 * (size_t)DM * DM, bo, out);
}

// round 15
// speedup vs baseline: 1.0842x; 1.0842x over previous
#include <cuda_runtime.h>
#include <cuda_fp16.h>
#include <math.h>

#define BATCH 4
#define SEQ   2048
#define DM    1024
#define NH    16
#define HD    64
#define MROWS (BATCH * SEQ)   // 8192

__device__ __half g_qkv[3][BATCH * NH * SEQ * HD];
__device__ __half g_ctx[MROWS * DM];
__device__ __half g_xh[MROWS * DM];
__device__ __half g_wth[4][DM * DM];       // fp16 TRANSPOSED weights [out][in]

// ---------------------------------------------------------------------------
// helpers
// ---------------------------------------------------------------------------
__device__ __forceinline__ unsigned h2pack(float a, float b) {
    __half2 h = __floats2half2_rn(a, b);
    return *(unsigned*)&h;
}

__device__ __forceinline__ void mma_fp16(float* d, const unsigned* a,
                                         unsigned b0, unsigned b1) {
    asm volatile(
        "mma.sync.aligned.m16n8k16.row.col.f32.f16.f16.f32 "
        "{%0,%1,%2,%3}, {%4,%5,%6,%7}, {%8,%9}, {%0,%1,%2,%3};\n"
        : "+f"(d[0]), "+f"(d[1]), "+f"(d[2]), "+f"(d[3])
        : "r"(a[0]), "r"(a[1]), "r"(a[2]), "r"(a[3]), "r"(b0), "r"(b1));
}

__device__ __forceinline__ unsigned ex2_f16x2(unsigned x) {
    unsigned r;
    asm("ex2.approx.f16x2 %0, %1;" : "=r"(r) : "r"(x));
    return r;
}

__device__ __forceinline__ unsigned saddr(const void* p) {
    return (unsigned)__cvta_generic_to_shared(p);
}
__device__ __forceinline__ void cp16(unsigned d, const void* s) {
    asm volatile("cp.async.cg.shared.global [%0], [%1], 16;" :: "r"(d), "l"(s));
}
#define CP_COMMIT asm volatile("cp.async.commit_group;")
#define CP_WAIT0  asm volatile("cp.async.wait_group 0;")
#define CP_WAIT1  asm volatile("cp.async.wait_group 1;")

__device__ __forceinline__ void ldsm4(unsigned& r0, unsigned& r1,
                                      unsigned& r2, unsigned& r3, unsigned a) {
    asm volatile("ldmatrix.sync.aligned.m8n8.x4.shared.b16 {%0,%1,%2,%3}, [%4];"
                 : "=r"(r0), "=r"(r1), "=r"(r2), "=r"(r3) : "r"(a));
}
__device__ __forceinline__ void ldsm4t(unsigned& r0, unsigned& r1,
                                       unsigned& r2, unsigned& r3, unsigned a) {
    asm volatile("ldmatrix.sync.aligned.m8n8.x4.trans.shared.b16 {%0,%1,%2,%3}, [%4];"
                 : "=r"(r0), "=r"(r1), "=r"(r2), "=r"(r3) : "r"(a));
}

// ---------------------------------------------------------------------------
// preprocessing
// ---------------------------------------------------------------------------
__global__ void round_fp16_k(const float* __restrict__ in,
                             __half* __restrict__ out, int n4)
{
    int i = blockIdx.x * blockDim.x + threadIdx.x;
    if (i < n4) {
        float4 v = ((const float4*)in)[i];
        __half2* o = (__half2*)(out + i * 4);
        o[0] = __floats2half2_rn(v.x, v.y);
        o[1] = __floats2half2_rn(v.z, v.w);
    }
}

__global__ void transpose_fp16_k(const float* __restrict__ w0,
                                 const float* __restrict__ w1,
                                 const float* __restrict__ w2,
                                 const float* __restrict__ w3,
                                 __half* __restrict__ out)
{
    __shared__ float t[32][33];
    const float* in = (blockIdx.z == 0) ? w0 : (blockIdx.z == 1) ? w1
                    : (blockIdx.z == 2) ? w2 : w3;
    __half* o = out + (size_t)blockIdx.z * DM * DM;
    int bx = blockIdx.x * 32, by = blockIdx.y * 32;
    int tx = threadIdx.x;
#pragma unroll
    for (int i = threadIdx.y; i < 32; i += 8)
        t[i][tx] = in[(size_t)(by + i) * DM + bx + tx];
    __syncthreads();
#pragma unroll
    for (int i = threadIdx.y; i < 32; i += 8)
        o[(size_t)(bx + i) * DM + by + tx] = __float2half_rn(t[tx][i]);
}

// ---------------------------------------------------------------------------
// fp16 GEMM core (R11 config): 256 threads, 8 warps (4M x 2N),
// warp tile 32x64, BM=BN=128, BK=64 halves, 3-stage cp.async ring.
// ---------------------------------------------------------------------------
#define G_STR 72
#define G_TILE_B (128 * G_STR * 2)
#define G_STAGE_B (2 * G_TILE_B)
#define G_SMEM (3 * G_STAGE_B)            // 110592 B

__device__ __forceinline__ void gemm_stage(
    const __half* __restrict__ A, const __half* __restrict__ Bt,
    unsigned stageBase, int rowBase, int colBase, int k0, int tid)
{
    unsigned Ab = stageBase;
    unsigned Bb = stageBase + G_TILE_B;
#pragma unroll
    for (int it = 0; it < 4; it++) {
        int idx = tid + it * 256;
        int r   = idx >> 3;
        int c8  = (idx & 7) * 8;
        cp16(Ab + (unsigned)(r * G_STR + c8) * 2,
             A  + (size_t)(rowBase + r) * DM + k0 + c8);
        cp16(Bb + (unsigned)(r * G_STR + c8) * 2,
             Bt + (size_t)(colBase + r) * DM + k0 + c8);
    }
}

struct GemmOut {
    float d[2][8][4];
};

__device__ __forceinline__ void gemm_core(
    const __half* A, const __half* Bt, unsigned s0,
    int rowBase, int colBase, int tid, int lane, int warpM, int warpN,
    GemmOut& o)
{
#pragma unroll
    for (int mt = 0; mt < 2; mt++)
#pragma unroll
        for (int nt = 0; nt < 8; nt++)
#pragma unroll
            for (int j = 0; j < 4; j++) o.d[mt][nt][j] = 0.f;

    const unsigned aOff =
        ((unsigned)((warpM * 32 + (lane & 15)) * G_STR + (lane >> 4) * 8)) * 2u;
    const unsigned bOff = G_TILE_B +
        ((unsigned)((warpN * 64 + (lane & 7) + ((lane >> 4) & 1) * 8) * G_STR
                    + ((lane >> 3) & 1) * 8)) * 2u;

    gemm_stage(A, Bt, s0,             rowBase, colBase, 0,  tid); CP_COMMIT;
    gemm_stage(A, Bt, s0 + G_STAGE_B, rowBase, colBase, 64, tid); CP_COMMIT;

    for (int itn = 0; itn < 16; itn++) {
        const unsigned stg = s0 + (unsigned)(itn % 3) * G_STAGE_B;
        if (itn >= 14) { CP_WAIT0; } else { CP_WAIT1; }
        __syncthreads();
        if (itn + 2 < 16) {
            gemm_stage(A, Bt, s0 + (unsigned)((itn + 2) % 3) * G_STAGE_B,
                       rowBase, colBase, (itn + 2) * 64, tid);
            CP_COMMIT;
        }
        const unsigned aB = stg + aOff;
        const unsigned bB = stg + bOff;

#pragma unroll
        for (int kk = 0; kk < 4; kk++) {
            unsigned a0[4], a1[4];
            ldsm4(a0[0], a0[1], a0[2], a0[3], aB + kk * 32);
            ldsm4(a1[0], a1[1], a1[2], a1[3], aB + 16 * G_STR * 2 + kk * 32);
#pragma unroll
            for (int p = 0; p < 4; p++) {
                unsigned r0, r1, r2, r3;
                ldsm4(r0, r1, r2, r3, bB + p * 16 * G_STR * 2 + kk * 32);
                mma_fp16(o.d[0][2 * p],     a0, r0, r1);
                mma_fp16(o.d[0][2 * p + 1], a0, r2, r3);
                mma_fp16(o.d[1][2 * p],     a1, r0, r1);
                mma_fp16(o.d[1][2 * p + 1], a1, r2, r3);
            }
        }
    }
}

// ---------------------------------------------------------------------------
// QKV GEMM with smem-staged, coalesced scatter epilogue.
// C tile staged as [128][136] halves; copy phase writes one contiguous
// 128B (b,h,s) row-segment per 8-lane group.
// ---------------------------------------------------------------------------
#define CS_STR 136   // halves; bank map (4r + t) mod 32 all-distinct

__global__ __launch_bounds__(256, 2) void gemm_qkv(
    const __half* __restrict__ A, const __half* __restrict__ WtBase,
    const float* __restrict__ bq, const float* __restrict__ bk,
    const float* __restrict__ bv, __half* __restrict__ Obase)
{
    extern __shared__ __half gsm[];
    const unsigned s0 = saddr(gsm);

    const int z = blockIdx.z;
    const __half* Bt = WtBase + (size_t)z * DM * DM;
    const float* bias = (z == 0) ? bq : (z == 1) ? bk : bv;
    __half* C = Obase + (size_t)z * (BATCH * NH * SEQ * HD);
    const float scale = (z == 0) ? 0.125f * 1.4426950408889634f : 1.0f;

    const int tid   = threadIdx.x;
    const int lane  = tid & 31;
    const int warp  = tid >> 5;
    const int warpM = warp & 3;
    const int warpN = warp >> 2;
    const int g     = lane >> 2;
    const int t     = lane & 3;
    const int rowBase = blockIdx.y * 128;
    const int colBase = blockIdx.x * 128;

    GemmOut o;
    gemm_core(A, Bt, s0, rowBase, colBase, tid, lane, warpM, warpN, o);

    __syncthreads();   // mainloop smem reads done; reuse ring as C stage

    // stage accumulators (bias+scale applied) into Cs[128][CS_STR]
#pragma unroll
    for (int mt = 0; mt < 2; mt++) {
        int r0 = warpM * 32 + mt * 16 + g;
#pragma unroll
        for (int nt = 0; nt < 8; nt++) {
            int c = warpN * 64 + nt * 8 + 2 * t;
            float bb0 = bias[colBase + c], bb1 = bias[colBase + c + 1];
            *(unsigned*)&gsm[r0 * CS_STR + c] =
                h2pack((o.d[mt][nt][0] + bb0) * scale,
                       (o.d[mt][nt][1] + bb1) * scale);
            *(unsigned*)&gsm[(r0 + 8) * CS_STR + c] =
                h2pack((o.d[mt][nt][2] + bb0) * scale,
                       (o.d[mt][nt][3] + bb1) * scale);
        }
    }
    __syncthreads();

    // coalesced copy-out: 16 lanes per row, 8 halves (16B) per lane
#pragma unroll
    for (int pass = 0; pass < 8; pass++) {
        int r     = pass * 16 + (tid >> 4);      // 0..127
        int col8  = (tid & 15) * 8;              // 0..120
        int row   = rowBase + r;
        int col   = colBase + col8;
        int h = col >> 6, hd = col & 63;
        int b = row >> 11, s = row & 2047;
        uint4 v = *(uint4*)&gsm[r * CS_STR + col8];
        *(uint4*)(C + (((size_t)(b * NH + h) * SEQ) + s) * HD + hd) = v;
    }
}

// ---------------------------------------------------------------------------
// Output GEMM: smem-staged fp32 epilogue, one warp writes one 512B row chunk.
// ---------------------------------------------------------------------------
#define CSF_STR 132  // floats

__global__ __launch_bounds__(256, 2) void gemm_out(
    const __half* __restrict__ A, const __half* __restrict__ Bt,
    const float* __restrict__ bias, float* __restrict__ C)
{
    extern __shared__ __half gsm[];
    float* Cs = (float*)gsm;
    const unsigned s0 = saddr(gsm);

    const int tid   = threadIdx.x;
    const int lane  = tid & 31;
    const int warp  = tid >> 5;
    const int warpM = warp & 3;
    const int warpN = warp >> 2;
    const int g     = lane >> 2;
    const int t     = lane & 3;
    const int rowBase = blockIdx.y * 128;
    const int colBase = blockIdx.x * 128;

    GemmOut o;
    gemm_core(A, Bt, s0, rowBase, colBase, tid, lane, warpM, warpN, o);

    __syncthreads();

#pragma unroll
    for (int mt = 0; mt < 2; mt++) {
        int r0 = warpM * 32 + mt * 16 + g;
#pragma unroll
        for (int nt = 0; nt < 8; nt++) {
            int c = warpN * 64 + nt * 8 + 2 * t;
            float bb0 = bias[colBase + c], bb1 = bias[colBase + c + 1];
            *(float2*)&Cs[r0 * CSF_STR + c] =
                make_float2(o.d[mt][nt][0] + bb0, o.d[mt][nt][1] + bb1);
            *(float2*)&Cs[(r0 + 8) * CSF_STR + c] =
                make_float2(o.d[mt][nt][2] + bb0, o.d[mt][nt][3] + bb1);
        }
    }
    __syncthreads();

    // copy-out: one warp per row (128 floats = 512B contiguous)
#pragma unroll
    for (int pass = 0; pass < 16; pass++) {
        int r = pass * 8 + warp;                 // 0..127
        float4 v = *(float4*)&Cs[r * CSF_STR + lane * 4];
        *(float4*)(C + (size_t)(rowBase + r) * DM + colBase + lane * 4) = v;
    }
}

// ---------------------------------------------------------------------------
// Flash attention fp16 (unchanged from R11): 64q x 64k, 128 threads,
// 4 CTAs/SM, ex2.f16x2 softmax, row-sum l via all-ones MMA column.
// ---------------------------------------------------------------------------
#define F_STR 72
#define FQ_B (64 * F_STR * 2)
#define FK_B (64 * F_STR * 2)
#define FA_SMEM (FQ_B + 4 * FK_B)  // 46080

#define ONES_H2 0x3C003C00u

__device__ __forceinline__ void fa_stage(
    const __half* __restrict__ Kb, const __half* __restrict__ Vb,
    unsigned Kd, unsigned Vd, int tid)
{
#pragma unroll
    for (int it = 0; it < 4; it++) {
        int idx = tid + it * 128;
        int r   = idx >> 3;
        int c8  = (idx & 7) * 8;
        cp16(Kd + (unsigned)(r * F_STR + c8) * 2, Kb + r * HD + c8);
        cp16(Vd + (unsigned)(r * F_STR + c8) * 2, Vb + r * HD + c8);
    }
}

__global__ __launch_bounds__(128, 4) void flash_fp16(
    const __half* __restrict__ Q, const __half* __restrict__ K,
    const __half* __restrict__ V, __half* __restrict__ ctx)
{
    extern __shared__ __half fsm[];
    const unsigned sQ = saddr(fsm);
    const unsigned sK = sQ + FQ_B;
    const unsigned sV = sK + 2 * FK_B;

    const int tid  = threadIdx.x;
    const int lane = tid & 31;
    const int warp = tid >> 5;
    const int g    = lane >> 2;
    const int t    = lane & 3;
    const int qt   = blockIdx.x;
    const int bh   = blockIdx.y;
    const int Q0   = qt * 64;
    const int rb   = warp * 16;

    const size_t base = (size_t)bh * SEQ * HD;

    const unsigned qAddr = sQ +
        ((unsigned)((rb + (lane & 15)) * F_STR + (lane >> 4) * 8)) * 2u;
    const unsigned kOff =
        ((unsigned)(((lane & 7) + ((lane >> 4) & 1) * 8) * F_STR
                    + ((lane >> 3) & 1) * 8)) * 2u;
    const unsigned vOff =
        ((unsigned)(((lane & 7) + ((lane >> 3) & 1) * 8) * F_STR
                    + (lane >> 4) * 8)) * 2u;

    {
        const __half* Qb = Q + base + (size_t)Q0 * HD;
#pragma unroll
        for (int it = 0; it < 4; it++) {
            int idx = tid + it * 128;
            int r   = idx >> 3;
            int c8  = (idx & 7) * 8;
            cp16(sQ + (unsigned)(r * F_STR + c8) * 2, Qb + r * HD + c8);
        }
        fa_stage(K + base, V + base, sK, sV, tid);
        CP_COMMIT;
    }

    float m[2] = {-INFINITY, -INFINITY};
    float O[9][4];
#pragma unroll
    for (int nf = 0; nf < 9; nf++)
#pragma unroll
        for (int j = 0; j < 4; j++) O[nf][j] = 0.f;

    int buf = 0;
    for (int kt = 0; kt <= qt; kt++) {
        CP_WAIT0;
        __syncthreads();
        if (kt < qt) {
            fa_stage(K + base + (size_t)(kt + 1) * 64 * HD,
                     V + base + (size_t)(kt + 1) * 64 * HD,
                     sK + (buf ^ 1) * FK_B, sV + (buf ^ 1) * FK_B, tid);
            CP_COMMIT;
        }
        const unsigned kB = sK + buf * FK_B + kOff;
        const unsigned vB = sV + buf * FK_B + vOff;

        float S[8][4];
#pragma unroll
        for (int nf = 0; nf < 8; nf++)
#pragma unroll
            for (int j = 0; j < 4; j++) S[nf][j] = 0.f;

#pragma unroll
        for (int kk = 0; kk < 4; kk++) {
            unsigned a[4];
            ldsm4(a[0], a[1], a[2], a[3], qAddr + kk * 32);
#pragma unroll
            for (int p = 0; p < 4; p++) {
                unsigned r0, r1, r2, r3;
                ldsm4(r0, r1, r2, r3, kB + p * 16 * F_STR * 2 + kk * 32);
                mma_fp16(S[2 * p],     a, r0, r1);
                mma_fp16(S[2 * p + 1], a, r2, r3);
            }
        }

        if (kt == qt) {
            int kb = kt * 64;
            int rlo = Q0 + rb + g, rhi = rlo + 8;
#pragma unroll
            for (int nf = 0; nf < 8; nf++) {
                int k0 = kb + nf * 8 + 2 * t;
                if (k0     > rlo) S[nf][0] = -INFINITY;
                if (k0 + 1 > rlo) S[nf][1] = -INFINITY;
                if (k0     > rhi) S[nf][2] = -INFINITY;
                if (k0 + 1 > rhi) S[nf][3] = -INFINITY;
            }
        }

        float sc0, sc1;
        {
            float mx0 = -INFINITY, mx1 = -INFINITY;
#pragma unroll
            for (int nf = 0; nf < 8; nf++) {
                mx0 = fmaxf(mx0, fmaxf(S[nf][0], S[nf][1]));
                mx1 = fmaxf(mx1, fmaxf(S[nf][2], S[nf][3]));
            }
            mx0 = fmaxf(mx0, __shfl_xor_sync(0xffffffffu, mx0, 1));
            mx0 = fmaxf(mx0, __shfl_xor_sync(0xffffffffu, mx0, 2));
            mx1 = fmaxf(mx1, __shfl_xor_sync(0xffffffffu, mx1, 1));
            mx1 = fmaxf(mx1, __shfl_xor_sync(0xffffffffu, mx1, 2));
            float mn0 = fmaxf(m[0], mx0);
            float mn1 = fmaxf(m[1], mx1);
            sc0 = exp2f(m[0] - mn0);
            sc1 = exp2f(m[1] - mn1);
            m[0] = mn0; m[1] = mn1;
        }

        unsigned E[8][2];
        {
            __half2 hm0 = __float2half2_rn(m[0]);
            __half2 hm1 = __float2half2_rn(m[1]);
#pragma unroll
            for (int nf = 0; nf < 8; nf++) {
                __half2 p0 = __floats2half2_rn(S[nf][0], S[nf][1]);
                __half2 p1 = __floats2half2_rn(S[nf][2], S[nf][3]);
                p0 = __hsub2(p0, hm0);
                p1 = __hsub2(p1, hm1);
                E[nf][0] = ex2_f16x2(*(unsigned*)&p0);
                E[nf][1] = ex2_f16x2(*(unsigned*)&p1);
            }
        }

#pragma unroll
        for (int nf = 0; nf < 9; nf++) {
            O[nf][0] *= sc0; O[nf][1] *= sc0;
            O[nf][2] *= sc1; O[nf][3] *= sc1;
        }

#pragma unroll
        for (int mkey = 0; mkey < 4; mkey++) {
            unsigned a[4];
            a[0] = E[2 * mkey][0];
            a[1] = E[2 * mkey][1];
            a[2] = E[2 * mkey + 1][0];
            a[3] = E[2 * mkey + 1][1];
#pragma unroll
            for (int p = 0; p < 4; p++) {
                unsigned r0, r1, r2, r3;
                ldsm4t(r0, r1, r2, r3,
                       vB + (mkey * 16 * F_STR + p * 16) * 2);
                mma_fp16(O[2 * p],     a, r0, r1);
                mma_fp16(O[2 * p + 1], a, r2, r3);
            }
            mma_fp16(O[8], a, ONES_H2, ONES_H2);
        }
        buf ^= 1;
    }

    const int b = bh >> 4, hh = bh & 15;
    const float inv0 = 1.f / O[8][0];
    const float inv1 = 1.f / O[8][2];
#pragma unroll
    for (int h2 = 0; h2 < 2; h2++) {
        float inv = h2 ? inv1 : inv0;
        int row = Q0 + rb + g + 8 * h2;
        __half* dst = ctx + ((size_t)(b * SEQ + row)) * DM + hh * HD;
#pragma unroll
        for (int nf = 0; nf < 8; nf++) {
            int c = nf * 8 + 2 * t;
            *(unsigned*)(dst + c) =
                h2pack(O[nf][2 * h2] * inv, O[nf][2 * h2 + 1] * inv);
        }
    }
}

// ---------------------------------------------------------------------------
// Launch
// ---------------------------------------------------------------------------
extern "C" void kernel_launch(void* const* d_in, const int* in_sizes, int n_in,
                              void* d_out, int out_size)
{
    const float* x  = (const float*)d_in[0];
    const float* wq = (const float*)d_in[1];
    const float* bq = (const float*)d_in[2];
    const float* wk = (const float*)d_in[3];
    const float* bk = (const float*)d_in[4];
    const float* wv = (const float*)d_in[5];
    const float* bv = (const float*)d_in[6];
    const float* wo = (const float*)d_in[7];
    const float* bo = (const float*)d_in[8];
    float* out = (float*)d_out;

    __half *qkv, *ctx, *xh, *wth;
    cudaGetSymbolAddress((void**)&qkv, g_qkv);
    cudaGetSymbolAddress((void**)&ctx, g_ctx);
    cudaGetSymbolAddress((void**)&xh,  g_xh);
    cudaGetSymbolAddress((void**)&wth, g_wth);
    const size_t HSZ = (size_t)BATCH * NH * SEQ * HD;

    cudaFuncSetAttribute(gemm_qkv,
                         cudaFuncAttributeMaxDynamicSharedMemorySize, G_SMEM);
    cudaFuncSetAttribute(gemm_out,
                         cudaFuncAttributeMaxDynamicSharedMemorySize, G_SMEM);
    cudaFuncSetAttribute(flash_fp16,
                         cudaFuncAttributeMaxDynamicSharedMemorySize, FA_SMEM);

    {
        int n4x = MROWS * DM / 4;
        round_fp16_k<<<(n4x + 255) / 256, 256>>>(x, xh, n4x);
        transpose_fp16_k<<<dim3(32, 32, 4), dim3(32, 8)>>>(wq, wk, wv, wo, wth);
    }

    gemm_qkv<<<dim3(DM / 128, MROWS / 128, 3), 256, G_SMEM>>>(
        xh, wth, bq, bk, bv, qkv);

    flash_fp16<<<dim3(SEQ / 64, BATCH * NH), 128, FA_SMEM>>>(
        qkv, qkv + HSZ, qkv + 2 * HSZ, ctx);

    gemm_out<<<dim3(DM / 128, MROWS / 128), 256, G_SMEM>>>(
        ctx, wth + 3 * (size_t)DM * DM, bo, out);
}

// round 16
// speedup vs baseline: 1.1299x; 1.0421x over previous
#include <cuda_runtime.h>
#include <cuda_fp16.h>
#include <math.h>

#define BATCH 4
#define SEQ   2048
#define DM    1024
#define NH    16
#define HD    64
#define MROWS (BATCH * SEQ)   // 8192
#define NT    (SEQ / 64)      // 32 key/query tiles

__device__ __half g_qkv[3][BATCH * NH * SEQ * HD];
__device__ __half g_ctx[MROWS * DM];
__device__ __half g_xh[MROWS * DM];
__device__ __half g_wth[4][DM * DM];       // fp16 TRANSPOSED weights [out][in]

// ---------------------------------------------------------------------------
// helpers
// ---------------------------------------------------------------------------
__device__ __forceinline__ unsigned h2pack(float a, float b) {
    __half2 h = __floats2half2_rn(a, b);
    return *(unsigned*)&h;
}

__device__ __forceinline__ void mma_fp16(float* d, const unsigned* a,
                                         unsigned b0, unsigned b1) {
    asm volatile(
        "mma.sync.aligned.m16n8k16.row.col.f32.f16.f16.f32 "
        "{%0,%1,%2,%3}, {%4,%5,%6,%7}, {%8,%9}, {%0,%1,%2,%3};\n"
        : "+f"(d[0]), "+f"(d[1]), "+f"(d[2]), "+f"(d[3])
        : "r"(a[0]), "r"(a[1]), "r"(a[2]), "r"(a[3]), "r"(b0), "r"(b1));
}

__device__ __forceinline__ unsigned ex2_f16x2(unsigned x) {
    unsigned r;
    asm("ex2.approx.f16x2 %0, %1;" : "=r"(r) : "r"(x));
    return r;
}

__device__ __forceinline__ unsigned saddr(const void* p) {
    return (unsigned)__cvta_generic_to_shared(p);
}
__device__ __forceinline__ void cp16(unsigned d, const void* s) {
    asm volatile("cp.async.cg.shared.global [%0], [%1], 16;" :: "r"(d), "l"(s));
}
#define CP_COMMIT asm volatile("cp.async.commit_group;")
#define CP_WAIT0  asm volatile("cp.async.wait_group 0;")
#define CP_WAIT1  asm volatile("cp.async.wait_group 1;")

__device__ __forceinline__ void ldsm4(unsigned& r0, unsigned& r1,
                                      unsigned& r2, unsigned& r3, unsigned a) {
    asm volatile("ldmatrix.sync.aligned.m8n8.x4.shared.b16 {%0,%1,%2,%3}, [%4];"
                 : "=r"(r0), "=r"(r1), "=r"(r2), "=r"(r3) : "r"(a));
}
__device__ __forceinline__ void ldsm4t(unsigned& r0, unsigned& r1,
                                       unsigned& r2, unsigned& r3, unsigned a) {
    asm volatile("ldmatrix.sync.aligned.m8n8.x4.trans.shared.b16 {%0,%1,%2,%3}, [%4];"
                 : "=r"(r0), "=r"(r1), "=r"(r2), "=r"(r3) : "r"(a));
}

// ---------------------------------------------------------------------------
// preprocessing
// ---------------------------------------------------------------------------
__global__ void round_fp16_k(const float* __restrict__ in,
                             __half* __restrict__ out, int n4)
{
    int i = blockIdx.x * blockDim.x + threadIdx.x;
    if (i < n4) {
        float4 v = ((const float4*)in)[i];
        __half2* o = (__half2*)(out + i * 4);
        o[0] = __floats2half2_rn(v.x, v.y);
        o[1] = __floats2half2_rn(v.z, v.w);
    }
}

__global__ void transpose_fp16_k(const float* __restrict__ w0,
                                 const float* __restrict__ w1,
                                 const float* __restrict__ w2,
                                 const float* __restrict__ w3,
                                 __half* __restrict__ out)
{
    __shared__ float t[32][33];
    const float* in = (blockIdx.z == 0) ? w0 : (blockIdx.z == 1) ? w1
                    : (blockIdx.z == 2) ? w2 : w3;
    __half* o = out + (size_t)blockIdx.z * DM * DM;
    int bx = blockIdx.x * 32, by = blockIdx.y * 32;
    int tx = threadIdx.x;
#pragma unroll
    for (int i = threadIdx.y; i < 32; i += 8)
        t[i][tx] = in[(size_t)(by + i) * DM + bx + tx];
    __syncthreads();
#pragma unroll
    for (int i = threadIdx.y; i < 32; i += 8)
        o[(size_t)(bx + i) * DM + by + tx] = __float2half_rn(t[tx][i]);
}

// ---------------------------------------------------------------------------
// fp16 GEMM core (R11 config): 256 threads, 8 warps (4M x 2N),
// warp tile 32x64, BM=BN=128, BK=64 halves, 3-stage cp.async ring.
// ---------------------------------------------------------------------------
#define G_STR 72
#define G_TILE_B (128 * G_STR * 2)
#define G_STAGE_B (2 * G_TILE_B)
#define G_SMEM (3 * G_STAGE_B)            // 110592 B

__device__ __forceinline__ void gemm_stage(
    const __half* __restrict__ A, const __half* __restrict__ Bt,
    unsigned stageBase, int rowBase, int colBase, int k0, int tid)
{
    unsigned Ab = stageBase;
    unsigned Bb = stageBase + G_TILE_B;
#pragma unroll
    for (int it = 0; it < 4; it++) {
        int idx = tid + it * 256;
        int r   = idx >> 3;
        int c8  = (idx & 7) * 8;
        cp16(Ab + (unsigned)(r * G_STR + c8) * 2,
             A  + (size_t)(rowBase + r) * DM + k0 + c8);
        cp16(Bb + (unsigned)(r * G_STR + c8) * 2,
             Bt + (size_t)(colBase + r) * DM + k0 + c8);
    }
}

struct GemmOut {
    float d[2][8][4];
};

__device__ __forceinline__ void gemm_core(
    const __half* A, const __half* Bt, unsigned s0,
    int rowBase, int colBase, int tid, int lane, int warpM, int warpN,
    GemmOut& o)
{
#pragma unroll
    for (int mt = 0; mt < 2; mt++)
#pragma unroll
        for (int nt = 0; nt < 8; nt++)
#pragma unroll
            for (int j = 0; j < 4; j++) o.d[mt][nt][j] = 0.f;

    const unsigned aOff =
        ((unsigned)((warpM * 32 + (lane & 15)) * G_STR + (lane >> 4) * 8)) * 2u;
    const unsigned bOff = G_TILE_B +
        ((unsigned)((warpN * 64 + (lane & 7) + ((lane >> 4) & 1) * 8) * G_STR
                    + ((lane >> 3) & 1) * 8)) * 2u;

    gemm_stage(A, Bt, s0,             rowBase, colBase, 0,  tid); CP_COMMIT;
    gemm_stage(A, Bt, s0 + G_STAGE_B, rowBase, colBase, 64, tid); CP_COMMIT;

    for (int itn = 0; itn < 16; itn++) {
        const unsigned stg = s0 + (unsigned)(itn % 3) * G_STAGE_B;
        if (itn >= 14) { CP_WAIT0; } else { CP_WAIT1; }
        __syncthreads();
        if (itn + 2 < 16) {
            gemm_stage(A, Bt, s0 + (unsigned)((itn + 2) % 3) * G_STAGE_B,
                       rowBase, colBase, (itn + 2) * 64, tid);
            CP_COMMIT;
        }
        const unsigned aB = stg + aOff;
        const unsigned bB = stg + bOff;

#pragma unroll
        for (int kk = 0; kk < 4; kk++) {
            unsigned a0[4], a1[4];
            ldsm4(a0[0], a0[1], a0[2], a0[3], aB + kk * 32);
            ldsm4(a1[0], a1[1], a1[2], a1[3], aB + 16 * G_STR * 2 + kk * 32);
#pragma unroll
            for (int p = 0; p < 4; p++) {
                unsigned r0, r1, r2, r3;
                ldsm4(r0, r1, r2, r3, bB + p * 16 * G_STR * 2 + kk * 32);
                mma_fp16(o.d[0][2 * p],     a0, r0, r1);
                mma_fp16(o.d[0][2 * p + 1], a0, r2, r3);
                mma_fp16(o.d[1][2 * p],     a1, r0, r1);
                mma_fp16(o.d[1][2 * p + 1], a1, r2, r3);
            }
        }
    }
}

// ---------------------------------------------------------------------------
// QKV GEMM with smem-staged, coalesced scatter epilogue (R14).
// ---------------------------------------------------------------------------
#define CS_STR 136   // halves

__global__ __launch_bounds__(256, 2) void gemm_qkv(
    const __half* __restrict__ A, const __half* __restrict__ WtBase,
    const float* __restrict__ bq, const float* __restrict__ bk,
    const float* __restrict__ bv, __half* __restrict__ Obase)
{
    extern __shared__ __half gsm[];
    const unsigned s0 = saddr(gsm);

    const int z = blockIdx.z;
    const __half* Bt = WtBase + (size_t)z * DM * DM;
    const float* bias = (z == 0) ? bq : (z == 1) ? bk : bv;
    __half* C = Obase + (size_t)z * (BATCH * NH * SEQ * HD);
    const float scale = (z == 0) ? 0.125f * 1.4426950408889634f : 1.0f;

    const int tid   = threadIdx.x;
    const int lane  = tid & 31;
    const int warp  = tid >> 5;
    const int warpM = warp & 3;
    const int warpN = warp >> 2;
    const int g     = lane >> 2;
    const int t     = lane & 3;
    const int rowBase = blockIdx.y * 128;
    const int colBase = blockIdx.x * 128;

    GemmOut o;
    gemm_core(A, Bt, s0, rowBase, colBase, tid, lane, warpM, warpN, o);

    __syncthreads();

#pragma unroll
    for (int mt = 0; mt < 2; mt++) {
        int r0 = warpM * 32 + mt * 16 + g;
#pragma unroll
        for (int nt = 0; nt < 8; nt++) {
            int c = warpN * 64 + nt * 8 + 2 * t;
            float bb0 = bias[colBase + c], bb1 = bias[colBase + c + 1];
            *(unsigned*)&gsm[r0 * CS_STR + c] =
                h2pack((o.d[mt][nt][0] + bb0) * scale,
                       (o.d[mt][nt][1] + bb1) * scale);
            *(unsigned*)&gsm[(r0 + 8) * CS_STR + c] =
                h2pack((o.d[mt][nt][2] + bb0) * scale,
                       (o.d[mt][nt][3] + bb1) * scale);
        }
    }
    __syncthreads();

#pragma unroll
    for (int pass = 0; pass < 8; pass++) {
        int r     = pass * 16 + (tid >> 4);
        int col8  = (tid & 15) * 8;
        int row   = rowBase + r;
        int col   = colBase + col8;
        int h = col >> 6, hd = col & 63;
        int b = row >> 11, s = row & 2047;
        uint4 v = *(uint4*)&gsm[r * CS_STR + col8];
        *(uint4*)(C + (((size_t)(b * NH + h) * SEQ) + s) * HD + hd) = v;
    }
}

// ---------------------------------------------------------------------------
// Output GEMM: smem-staged fp32 epilogue (R14).
// ---------------------------------------------------------------------------
#define CSF_STR 132  // floats

__global__ __launch_bounds__(256, 2) void gemm_out(
    const __half* __restrict__ A, const __half* __restrict__ Bt,
    const float* __restrict__ bias, float* __restrict__ C)
{
    extern __shared__ __half gsm[];
    float* Cs = (float*)gsm;
    const unsigned s0 = saddr(gsm);

    const int tid   = threadIdx.x;
    const int lane  = tid & 31;
    const int warp  = tid >> 5;
    const int warpM = warp & 3;
    const int warpN = warp >> 2;
    const int g     = lane >> 2;
    const int t     = lane & 3;
    const int rowBase = blockIdx.y * 128;
    const int colBase = blockIdx.x * 128;

    GemmOut o;
    gemm_core(A, Bt, s0, rowBase, colBase, tid, lane, warpM, warpN, o);

    __syncthreads();

#pragma unroll
    for (int mt = 0; mt < 2; mt++) {
        int r0 = warpM * 32 + mt * 16 + g;
#pragma unroll
        for (int nt = 0; nt < 8; nt++) {
            int c = warpN * 64 + nt * 8 + 2 * t;
            float bb0 = bias[colBase + c], bb1 = bias[colBase + c + 1];
            *(float2*)&Cs[r0 * CSF_STR + c] =
                make_float2(o.d[mt][nt][0] + bb0, o.d[mt][nt][1] + bb1);
            *(float2*)&Cs[(r0 + 8) * CSF_STR + c] =
                make_float2(o.d[mt][nt][2] + bb0, o.d[mt][nt][3] + bb1);
        }
    }
    __syncthreads();

#pragma unroll
    for (int pass = 0; pass < 16; pass++) {
        int r = pass * 8 + warp;
        float4 v = *(float4*)&Cs[r * CSF_STR + lane * 4];
        *(float4*)(C + (size_t)(rowBase + r) * DM + colBase + lane * 4) = v;
    }
}

// ---------------------------------------------------------------------------
// Flash attention fp16, causal-balanced: each CTA processes the complementary
// pair (qt, NT-1-qt) sequentially -> uniform 33 k-tiles per CTA.
// 64q x 64k, 128 threads, 4 CTAs/SM, ex2.f16x2 softmax, mma row-sum l.
// ---------------------------------------------------------------------------
#define F_STR 72
#define FQ_B (64 * F_STR * 2)
#define FK_B (64 * F_STR * 2)
#define FA_SMEM (FQ_B + 4 * FK_B)  // 46080

#define ONES_H2 0x3C003C00u

__device__ __forceinline__ void fa_stage(
    const __half* __restrict__ Kb, const __half* __restrict__ Vb,
    unsigned Kd, unsigned Vd, int tid)
{
#pragma unroll
    for (int it = 0; it < 4; it++) {
        int idx = tid + it * 128;
        int r   = idx >> 3;
        int c8  = (idx & 7) * 8;
        cp16(Kd + (unsigned)(r * F_STR + c8) * 2, Kb + r * HD + c8);
        cp16(Vd + (unsigned)(r * F_STR + c8) * 2, Vb + r * HD + c8);
    }
}

__global__ __launch_bounds__(128, 4) void flash_fp16(
    const __half* __restrict__ Q, const __half* __restrict__ K,
    const __half* __restrict__ V, __half* __restrict__ ctx)
{
    extern __shared__ __half fsm[];
    const unsigned sQ = saddr(fsm);
    const unsigned sK = sQ + FQ_B;
    const unsigned sV = sK + 2 * FK_B;

    const int tid  = threadIdx.x;
    const int lane = tid & 31;
    const int warp = tid >> 5;
    const int g    = lane >> 2;
    const int t    = lane & 3;
    const int bh   = blockIdx.y;
    const int rb   = warp * 16;

    const size_t base = (size_t)bh * SEQ * HD;

    const unsigned qOff =
        ((unsigned)((rb + (lane & 15)) * F_STR + (lane >> 4) * 8)) * 2u;
    const unsigned kOff =
        ((unsigned)(((lane & 7) + ((lane >> 4) & 1) * 8) * F_STR
                    + ((lane >> 3) & 1) * 8)) * 2u;
    const unsigned vOff =
        ((unsigned)(((lane & 7) + ((lane >> 3) & 1) * 8) * F_STR
                    + (lane >> 4) * 8)) * 2u;

    const int b = bh >> 4, hh = bh & 15;

#pragma unroll 1
    for (int pass = 0; pass < 2; pass++) {
        const int qt = pass ? (NT - 1 - blockIdx.x) : blockIdx.x;
        const int Q0 = qt * 64;

        // prologue: stage Q + K/V tile 0
        {
            const __half* Qb = Q + base + (size_t)Q0 * HD;
#pragma unroll
            for (int it = 0; it < 4; it++) {
                int idx = tid + it * 128;
                int r   = idx >> 3;
                int c8  = (idx & 7) * 8;
                cp16(sQ + (unsigned)(r * F_STR + c8) * 2, Qb + r * HD + c8);
            }
            fa_stage(K + base, V + base, sK, sV, tid);
            CP_COMMIT;
        }

        float m[2] = {-INFINITY, -INFINITY};
        float O[9][4];
#pragma unroll
        for (int nf = 0; nf < 9; nf++)
#pragma unroll
            for (int j = 0; j < 4; j++) O[nf][j] = 0.f;

        int buf = 0;
        for (int kt = 0; kt <= qt; kt++) {
            CP_WAIT0;
            __syncthreads();
            if (kt < qt) {
                fa_stage(K + base + (size_t)(kt + 1) * 64 * HD,
                         V + base + (size_t)(kt + 1) * 64 * HD,
                         sK + (buf ^ 1) * FK_B, sV + (buf ^ 1) * FK_B, tid);
                CP_COMMIT;
            }
            const unsigned kB = sK + buf * FK_B + kOff;
            const unsigned vB = sV + buf * FK_B + vOff;
            const unsigned qA = sQ + qOff;

            float S[8][4];
#pragma unroll
            for (int nf = 0; nf < 8; nf++)
#pragma unroll
                for (int j = 0; j < 4; j++) S[nf][j] = 0.f;

#pragma unroll
            for (int kk = 0; kk < 4; kk++) {
                unsigned a[4];
                ldsm4(a[0], a[1], a[2], a[3], qA + kk * 32);
#pragma unroll
                for (int p = 0; p < 4; p++) {
                    unsigned r0, r1, r2, r3;
                    ldsm4(r0, r1, r2, r3, kB + p * 16 * F_STR * 2 + kk * 32);
                    mma_fp16(S[2 * p],     a, r0, r1);
                    mma_fp16(S[2 * p + 1], a, r2, r3);
                }
            }

            if (kt == qt) {
                int kb = kt * 64;
                int rlo = Q0 + rb + g, rhi = rlo + 8;
#pragma unroll
                for (int nf = 0; nf < 8; nf++) {
                    int k0 = kb + nf * 8 + 2 * t;
                    if (k0     > rlo) S[nf][0] = -INFINITY;
                    if (k0 + 1 > rlo) S[nf][1] = -INFINITY;
                    if (k0     > rhi) S[nf][2] = -INFINITY;
                    if (k0 + 1 > rhi) S[nf][3] = -INFINITY;
                }
            }

            float sc0, sc1;
            {
                float mx0 = -INFINITY, mx1 = -INFINITY;
#pragma unroll
                for (int nf = 0; nf < 8; nf++) {
                    mx0 = fmaxf(mx0, fmaxf(S[nf][0], S[nf][1]));
                    mx1 = fmaxf(mx1, fmaxf(S[nf][2], S[nf][3]));
                }
                mx0 = fmaxf(mx0, __shfl_xor_sync(0xffffffffu, mx0, 1));
                mx0 = fmaxf(mx0, __shfl_xor_sync(0xffffffffu, mx0, 2));
                mx1 = fmaxf(mx1, __shfl_xor_sync(0xffffffffu, mx1, 1));
                mx1 = fmaxf(mx1, __shfl_xor_sync(0xffffffffu, mx1, 2));
                float mn0 = fmaxf(m[0], mx0);
                float mn1 = fmaxf(m[1], mx1);
                sc0 = exp2f(m[0] - mn0);
                sc1 = exp2f(m[1] - mn1);
                m[0] = mn0; m[1] = mn1;
            }

            unsigned E[8][2];
            {
                __half2 hm0 = __float2half2_rn(m[0]);
                __half2 hm1 = __float2half2_rn(m[1]);
#pragma unroll
                for (int nf = 0; nf < 8; nf++) {
                    __half2 p0 = __floats2half2_rn(S[nf][0], S[nf][1]);
                    __half2 p1 = __floats2half2_rn(S[nf][2], S[nf][3]);
                    p0 = __hsub2(p0, hm0);
                    p1 = __hsub2(p1, hm1);
                    E[nf][0] = ex2_f16x2(*(unsigned*)&p0);
                    E[nf][1] = ex2_f16x2(*(unsigned*)&p1);
                }
            }

#pragma unroll
            for (int nf = 0; nf < 9; nf++) {
                O[nf][0] *= sc0; O[nf][1] *= sc0;
                O[nf][2] *= sc1; O[nf][3] *= sc1;
            }

#pragma unroll
            for (int mkey = 0; mkey < 4; mkey++) {
                unsigned a[4];
                a[0] = E[2 * mkey][0];
                a[1] = E[2 * mkey][1];
                a[2] = E[2 * mkey + 1][0];
                a[3] = E[2 * mkey + 1][1];
#pragma unroll
                for (int p = 0; p < 4; p++) {
                    unsigned r0, r1, r2, r3;
                    ldsm4t(r0, r1, r2, r3,
                           vB + (mkey * 16 * F_STR + p * 16) * 2);
                    mma_fp16(O[2 * p],     a, r0, r1);
                    mma_fp16(O[2 * p + 1], a, r2, r3);
                }
                mma_fp16(O[8], a, ONES_H2, ONES_H2);
            }
            buf ^= 1;
        }

        // epilogue for this pass
        const float inv0 = 1.f / O[8][0];
        const float inv1 = 1.f / O[8][2];
#pragma unroll
        for (int h2 = 0; h2 < 2; h2++) {
            float inv = h2 ? inv1 : inv0;
            int row = Q0 + rb + g + 8 * h2;
            __half* dst = ctx + ((size_t)(b * SEQ + row)) * DM + hh * HD;
#pragma unroll
            for (int nf = 0; nf < 8; nf++) {
                int c = nf * 8 + 2 * t;
                *(unsigned*)(dst + c) =
                    h2pack(O[nf][2 * h2] * inv, O[nf][2 * h2 + 1] * inv);
            }
        }

        __syncthreads();   // pass-1 readers done before pass-2 restages
    }
}

// ---------------------------------------------------------------------------
// Launch
// ---------------------------------------------------------------------------
extern "C" void kernel_launch(void* const* d_in, const int* in_sizes, int n_in,
                              void* d_out, int out_size)
{
    const float* x  = (const float*)d_in[0];
    const float* wq = (const float*)d_in[1];
    const float* bq = (const float*)d_in[2];
    const float* wk = (const float*)d_in[3];
    const float* bk = (const float*)d_in[4];
    const float* wv = (const float*)d_in[5];
    const float* bv = (const float*)d_in[6];
    const float* wo = (const float*)d_in[7];
    const float* bo = (const float*)d_in[8];
    float* out = (float*)d_out;

    __half *qkv, *ctx, *xh, *wth;
    cudaGetSymbolAddress((void**)&qkv, g_qkv);
    cudaGetSymbolAddress((void**)&ctx, g_ctx);
    cudaGetSymbolAddress((void**)&xh,  g_xh);
    cudaGetSymbolAddress((void**)&wth, g_wth);
    const size_t HSZ = (size_t)BATCH * NH * SEQ * HD;

    cudaFuncSetAttribute(gemm_qkv,
                         cudaFuncAttributeMaxDynamicSharedMemorySize, G_SMEM);
    cudaFuncSetAttribute(gemm_out,
                         cudaFuncAttributeMaxDynamicSharedMemorySize, G_SMEM);
    cudaFuncSetAttribute(flash_fp16,
                         cudaFuncAttributeMaxDynamicSharedMemorySize, FA_SMEM);

    {
        int n4x = MROWS * DM / 4;
        round_fp16_k<<<(n4x + 255) / 256, 256>>>(x, xh, n4x);
        transpose_fp16_k<<<dim3(32, 32, 4), dim3(32, 8)>>>(wq, wk, wv, wo, wth);
    }

    gemm_qkv<<<dim3(DM / 128, MROWS / 128, 3), 256, G_SMEM>>>(
        xh, wth, bq, bk, bv, qkv);

    flash_fp16<<<dim3(NT / 2, BATCH * NH), 128, FA_SMEM>>>(
        qkv, qkv + HSZ, qkv + 2 * HSZ, ctx);

    gemm_out<<<dim3(DM / 128, MROWS / 128), 256, G_SMEM>>>(
        ctx, wth + 3 * (size_t)DM * DM, bo, out);
}

// round 17
// speedup vs baseline: 1.1322x; 1.0020x over previous
#include <cuda_runtime.h>
#include <cuda_fp16.h>
#include <math.h>

#define BATCH 4
#define SEQ   2048
#define DM    1024
#define NH    16
#define HD    64
#define MROWS (BATCH * SEQ)   // 8192
#define NT    (SEQ / 64)      // 32 key/query tiles

__device__ __half g_qkv[3][BATCH * NH * SEQ * HD];
__device__ __half g_ctx[MROWS * DM];
__device__ __half g_xh[MROWS * DM];
__device__ __half g_wth[4][DM * DM];       // fp16 TRANSPOSED weights [out][in]

// ---------------------------------------------------------------------------
// helpers
// ---------------------------------------------------------------------------
__device__ __forceinline__ unsigned h2pack(float a, float b) {
    __half2 h = __floats2half2_rn(a, b);
    return *(unsigned*)&h;
}

__device__ __forceinline__ void mma_fp16(float* d, const unsigned* a,
                                         unsigned b0, unsigned b1) {
    asm volatile(
        "mma.sync.aligned.m16n8k16.row.col.f32.f16.f16.f32 "
        "{%0,%1,%2,%3}, {%4,%5,%6,%7}, {%8,%9}, {%0,%1,%2,%3};\n"
        : "+f"(d[0]), "+f"(d[1]), "+f"(d[2]), "+f"(d[3])
        : "r"(a[0]), "r"(a[1]), "r"(a[2]), "r"(a[3]), "r"(b0), "r"(b1));
}

__device__ __forceinline__ unsigned ex2_f16x2(unsigned x) {
    unsigned r;
    asm("ex2.approx.f16x2 %0, %1;" : "=r"(r) : "r"(x));
    return r;
}

__device__ __forceinline__ unsigned saddr(const void* p) {
    return (unsigned)__cvta_generic_to_shared(p);
}
__device__ __forceinline__ void cp16(unsigned d, const void* s) {
    asm volatile("cp.async.cg.shared.global [%0], [%1], 16;" :: "r"(d), "l"(s));
}
#define CP_COMMIT asm volatile("cp.async.commit_group;")
#define CP_WAIT0  asm volatile("cp.async.wait_group 0;")
#define CP_WAIT1  asm volatile("cp.async.wait_group 1;")

__device__ __forceinline__ void ldsm4(unsigned& r0, unsigned& r1,
                                      unsigned& r2, unsigned& r3, unsigned a) {
    asm volatile("ldmatrix.sync.aligned.m8n8.x4.shared.b16 {%0,%1,%2,%3}, [%4];"
                 : "=r"(r0), "=r"(r1), "=r"(r2), "=r"(r3) : "r"(a));
}
__device__ __forceinline__ void ldsm4t(unsigned& r0, unsigned& r1,
                                       unsigned& r2, unsigned& r3, unsigned a) {
    asm volatile("ldmatrix.sync.aligned.m8n8.x4.trans.shared.b16 {%0,%1,%2,%3}, [%4];"
                 : "=r"(r0), "=r"(r1), "=r"(r2), "=r"(r3) : "r"(a));
}

// ---------------------------------------------------------------------------
// merged preprocessing: z<4 -> transpose+round weight z; z==4 -> round x
// grid (32, 32, 5), block (32, 8)
// ---------------------------------------------------------------------------
__global__ void prep_k(const float* __restrict__ x,
                       const float* __restrict__ w0,
                       const float* __restrict__ w1,
                       const float* __restrict__ w2,
                       const float* __restrict__ w3,
                       __half* __restrict__ xh,
                       __half* __restrict__ wth)
{
    const int z = blockIdx.z;
    if (z < 4) {
        __shared__ float t[32][33];
        const float* in = (z == 0) ? w0 : (z == 1) ? w1 : (z == 2) ? w2 : w3;
        __half* o = wth + (size_t)z * DM * DM;
        int bx = blockIdx.x * 32, by = blockIdx.y * 32;
        int tx = threadIdx.x;
#pragma unroll
        for (int i = threadIdx.y; i < 32; i += 8)
            t[i][tx] = in[(size_t)(by + i) * DM + bx + tx];
        __syncthreads();
#pragma unroll
        for (int i = threadIdx.y; i < 32; i += 8)
            o[(size_t)(bx + i) * DM + by + tx] = __float2half_rn(t[tx][i]);
    } else {
        // x rounding: 1024 blocks x 256 threads x 8 float4 = 8M floats
        int blk = blockIdx.y * 32 + blockIdx.x;       // 0..1023
        int tid = threadIdx.y * 32 + threadIdx.x;     // 0..255
        int base = blk * 2048 + tid;                  // float4 index
#pragma unroll
        for (int i = 0; i < 8; i++) {
            int idx = base + i * 256;
            float4 v = ((const float4*)x)[idx];
            __half2* o = (__half2*)(xh + idx * 4);
            o[0] = __floats2half2_rn(v.x, v.y);
            o[1] = __floats2half2_rn(v.z, v.w);
        }
    }
}

// ---------------------------------------------------------------------------
// fp16 GEMM core (R11 config): 256 threads, 8 warps (4M x 2N),
// warp tile 32x64, BM=BN=128, BK=64 halves, 3-stage cp.async ring.
// ---------------------------------------------------------------------------
#define G_STR 72
#define G_TILE_B (128 * G_STR * 2)
#define G_STAGE_B (2 * G_TILE_B)
#define G_SMEM (3 * G_STAGE_B)            // 110592 B

__device__ __forceinline__ void gemm_stage(
    const __half* __restrict__ A, const __half* __restrict__ Bt,
    unsigned stageBase, int rowBase, int colBase, int k0, int tid)
{
    unsigned Ab = stageBase;
    unsigned Bb = stageBase + G_TILE_B;
#pragma unroll
    for (int it = 0; it < 4; it++) {
        int idx = tid + it * 256;
        int r   = idx >> 3;
        int c8  = (idx & 7) * 8;
        cp16(Ab + (unsigned)(r * G_STR + c8) * 2,
             A  + (size_t)(rowBase + r) * DM + k0 + c8);
        cp16(Bb + (unsigned)(r * G_STR + c8) * 2,
             Bt + (size_t)(colBase + r) * DM + k0 + c8);
    }
}

struct GemmOut {
    float d[2][8][4];
};

__device__ __forceinline__ void gemm_core(
    const __half* A, const __half* Bt, unsigned s0,
    int rowBase, int colBase, int tid, int lane, int warpM, int warpN,
    GemmOut& o)
{
#pragma unroll
    for (int mt = 0; mt < 2; mt++)
#pragma unroll
        for (int nt = 0; nt < 8; nt++)
#pragma unroll
            for (int j = 0; j < 4; j++) o.d[mt][nt][j] = 0.f;

    const unsigned aOff =
        ((unsigned)((warpM * 32 + (lane & 15)) * G_STR + (lane >> 4) * 8)) * 2u;
    const unsigned bOff = G_TILE_B +
        ((unsigned)((warpN * 64 + (lane & 7) + ((lane >> 4) & 1) * 8) * G_STR
                    + ((lane >> 3) & 1) * 8)) * 2u;

    gemm_stage(A, Bt, s0,             rowBase, colBase, 0,  tid); CP_COMMIT;
    gemm_stage(A, Bt, s0 + G_STAGE_B, rowBase, colBase, 64, tid); CP_COMMIT;

    for (int itn = 0; itn < 16; itn++) {
        const unsigned stg = s0 + (unsigned)(itn % 3) * G_STAGE_B;
        if (itn >= 14) { CP_WAIT0; } else { CP_WAIT1; }
        __syncthreads();
        if (itn + 2 < 16) {
            gemm_stage(A, Bt, s0 + (unsigned)((itn + 2) % 3) * G_STAGE_B,
                       rowBase, colBase, (itn + 2) * 64, tid);
            CP_COMMIT;
        }
        const unsigned aB = stg + aOff;
        const unsigned bB = stg + bOff;

#pragma unroll
        for (int kk = 0; kk < 4; kk++) {
            unsigned a0[4], a1[4];
            ldsm4(a0[0], a0[1], a0[2], a0[3], aB + kk * 32);
            ldsm4(a1[0], a1[1], a1[2], a1[3], aB + 16 * G_STR * 2 + kk * 32);
#pragma unroll
            for (int p = 0; p < 4; p++) {
                unsigned r0, r1, r2, r3;
                ldsm4(r0, r1, r2, r3, bB + p * 16 * G_STR * 2 + kk * 32);
                mma_fp16(o.d[0][2 * p],     a0, r0, r1);
                mma_fp16(o.d[0][2 * p + 1], a0, r2, r3);
                mma_fp16(o.d[1][2 * p],     a1, r0, r1);
                mma_fp16(o.d[1][2 * p + 1], a1, r2, r3);
            }
        }
    }
}

// ---------------------------------------------------------------------------
// QKV GEMM with smem-staged, coalesced scatter epilogue (R14).
// ---------------------------------------------------------------------------
#define CS_STR 136   // halves

__global__ __launch_bounds__(256, 2) void gemm_qkv(
    const __half* __restrict__ A, const __half* __restrict__ WtBase,
    const float* __restrict__ bq, const float* __restrict__ bk,
    const float* __restrict__ bv, __half* __restrict__ Obase)
{
    extern __shared__ __half gsm[];
    const unsigned s0 = saddr(gsm);

    const int z = blockIdx.z;
    const __half* Bt = WtBase + (size_t)z * DM * DM;
    const float* bias = (z == 0) ? bq : (z == 1) ? bk : bv;
    __half* C = Obase + (size_t)z * (BATCH * NH * SEQ * HD);
    const float scale = (z == 0) ? 0.125f * 1.4426950408889634f : 1.0f;

    const int tid   = threadIdx.x;
    const int lane  = tid & 31;
    const int warp  = tid >> 5;
    const int warpM = warp & 3;
    const int warpN = warp >> 2;
    const int g     = lane >> 2;
    const int t     = lane & 3;
    const int rowBase = blockIdx.y * 128;
    const int colBase = blockIdx.x * 128;

    GemmOut o;
    gemm_core(A, Bt, s0, rowBase, colBase, tid, lane, warpM, warpN, o);

    __syncthreads();

#pragma unroll
    for (int mt = 0; mt < 2; mt++) {
        int r0 = warpM * 32 + mt * 16 + g;
#pragma unroll
        for (int nt = 0; nt < 8; nt++) {
            int c = warpN * 64 + nt * 8 + 2 * t;
            float bb0 = bias[colBase + c], bb1 = bias[colBase + c + 1];
            *(unsigned*)&gsm[r0 * CS_STR + c] =
                h2pack((o.d[mt][nt][0] + bb0) * scale,
                       (o.d[mt][nt][1] + bb1) * scale);
            *(unsigned*)&gsm[(r0 + 8) * CS_STR + c] =
                h2pack((o.d[mt][nt][2] + bb0) * scale,
                       (o.d[mt][nt][3] + bb1) * scale);
        }
    }
    __syncthreads();

#pragma unroll
    for (int pass = 0; pass < 8; pass++) {
        int r     = pass * 16 + (tid >> 4);
        int col8  = (tid & 15) * 8;
        int row   = rowBase + r;
        int col   = colBase + col8;
        int h = col >> 6, hd = col & 63;
        int b = row >> 11, s = row & 2047;
        uint4 v = *(uint4*)&gsm[r * CS_STR + col8];
        *(uint4*)(C + (((size_t)(b * NH + h) * SEQ) + s) * HD + hd) = v;
    }
}

// ---------------------------------------------------------------------------
// Output GEMM: smem-staged fp32 epilogue (R14).
// ---------------------------------------------------------------------------
#define CSF_STR 132  // floats

__global__ __launch_bounds__(256, 2) void gemm_out(
    const __half* __restrict__ A, const __half* __restrict__ Bt,
    const float* __restrict__ bias, float* __restrict__ C)
{
    extern __shared__ __half gsm[];
    float* Cs = (float*)gsm;
    const unsigned s0 = saddr(gsm);

    const int tid   = threadIdx.x;
    const int lane  = tid & 31;
    const int warp  = tid >> 5;
    const int warpM = warp & 3;
    const int warpN = warp >> 2;
    const int g     = lane >> 2;
    const int t     = lane & 3;
    const int rowBase = blockIdx.y * 128;
    const int colBase = blockIdx.x * 128;

    GemmOut o;
    gemm_core(A, Bt, s0, rowBase, colBase, tid, lane, warpM, warpN, o);

    __syncthreads();

#pragma unroll
    for (int mt = 0; mt < 2; mt++) {
        int r0 = warpM * 32 + mt * 16 + g;
#pragma unroll
        for (int nt = 0; nt < 8; nt++) {
            int c = warpN * 64 + nt * 8 + 2 * t;
            float bb0 = bias[colBase + c], bb1 = bias[colBase + c + 1];
            *(float2*)&Cs[r0 * CSF_STR + c] =
                make_float2(o.d[mt][nt][0] + bb0, o.d[mt][nt][1] + bb1);
            *(float2*)&Cs[(r0 + 8) * CSF_STR + c] =
                make_float2(o.d[mt][nt][2] + bb0, o.d[mt][nt][3] + bb1);
        }
    }
    __syncthreads();

#pragma unroll
    for (int pass = 0; pass < 16; pass++) {
        int r = pass * 8 + warp;
        float4 v = *(float4*)&Cs[r * CSF_STR + lane * 4];
        *(float4*)(C + (size_t)(rowBase + r) * DM + colBase + lane * 4) = v;
    }
}

// ---------------------------------------------------------------------------
// Flash attention fp16, causal-balanced pairs + prefetch-distance-2 K/V.
// 64q x 64k, 128 threads, 4 CTAs/SM, ex2.f16x2 softmax, mma row-sum l.
// ---------------------------------------------------------------------------
#define F_STR 72
#define FQ_B (64 * F_STR * 2)
#define FK_B (64 * F_STR * 2)
#define FA_SMEM (FQ_B + 4 * FK_B)  // 46080

#define ONES_H2 0x3C003C00u

__device__ __forceinline__ void fa_stage(
    const __half* __restrict__ Kb, const __half* __restrict__ Vb,
    unsigned Kd, unsigned Vd, int tid)
{
#pragma unroll
    for (int it = 0; it < 4; it++) {
        int idx = tid + it * 128;
        int r   = idx >> 3;
        int c8  = (idx & 7) * 8;
        cp16(Kd + (unsigned)(r * F_STR + c8) * 2, Kb + r * HD + c8);
        cp16(Vd + (unsigned)(r * F_STR + c8) * 2, Vb + r * HD + c8);
    }
}

__global__ __launch_bounds__(128, 4) void flash_fp16(
    const __half* __restrict__ Q, const __half* __restrict__ K,
    const __half* __restrict__ V, __half* __restrict__ ctx)
{
    extern __shared__ __half fsm[];
    const unsigned sQ = saddr(fsm);
    const unsigned sK = sQ + FQ_B;
    const unsigned sV = sK + 2 * FK_B;

    const int tid  = threadIdx.x;
    const int lane = tid & 31;
    const int warp = tid >> 5;
    const int g    = lane >> 2;
    const int t    = lane & 3;
    const int bh   = blockIdx.y;
    const int rb   = warp * 16;

    const size_t base = (size_t)bh * SEQ * HD;

    const unsigned qOff =
        ((unsigned)((rb + (lane & 15)) * F_STR + (lane >> 4) * 8)) * 2u;
    const unsigned kOff =
        ((unsigned)(((lane & 7) + ((lane >> 4) & 1) * 8) * F_STR
                    + ((lane >> 3) & 1) * 8)) * 2u;
    const unsigned vOff =
        ((unsigned)(((lane & 7) + ((lane >> 3) & 1) * 8) * F_STR
                    + (lane >> 4) * 8)) * 2u;

    const int b = bh >> 4, hh = bh & 15;

#pragma unroll 1
    for (int pass = 0; pass < 2; pass++) {
        const int qt = pass ? (NT - 1 - blockIdx.x) : blockIdx.x;
        const int Q0 = qt * 64;

        // prologue: stage Q + KV0 (group A), then KV1 (group B) if present
        {
            const __half* Qb = Q + base + (size_t)Q0 * HD;
#pragma unroll
            for (int it = 0; it < 4; it++) {
                int idx = tid + it * 128;
                int r   = idx >> 3;
                int c8  = (idx & 7) * 8;
                cp16(sQ + (unsigned)(r * F_STR + c8) * 2, Qb + r * HD + c8);
            }
            fa_stage(K + base, V + base, sK, sV, tid);
            CP_COMMIT;
            if (qt >= 1) {
                fa_stage(K + base + (size_t)64 * HD, V + base + (size_t)64 * HD,
                         sK + FK_B, sV + FK_B, tid);
                CP_COMMIT;
            }
        }

        float m[2] = {-INFINITY, -INFINITY};
        float O[9][4];
#pragma unroll
        for (int nf = 0; nf < 9; nf++)
#pragma unroll
            for (int j = 0; j < 4; j++) O[nf][j] = 0.f;

        int buf = 0;
        for (int kt = 0; kt <= qt; kt++) {
            if (kt < qt) { CP_WAIT1; } else { CP_WAIT0; }
            __syncthreads();   // stage kt visible to all
            const unsigned kB = sK + buf * FK_B + kOff;
            const unsigned vB = sV + buf * FK_B + vOff;
            const unsigned qA = sQ + qOff;

            float S[8][4];
#pragma unroll
            for (int nf = 0; nf < 8; nf++)
#pragma unroll
                for (int j = 0; j < 4; j++) S[nf][j] = 0.f;

#pragma unroll
            for (int kk = 0; kk < 4; kk++) {
                unsigned a[4];
                ldsm4(a[0], a[1], a[2], a[3], qA + kk * 32);
#pragma unroll
                for (int p = 0; p < 4; p++) {
                    unsigned r0, r1, r2, r3;
                    ldsm4(r0, r1, r2, r3, kB + p * 16 * F_STR * 2 + kk * 32);
                    mma_fp16(S[2 * p],     a, r0, r1);
                    mma_fp16(S[2 * p + 1], a, r2, r3);
                }
            }

            if (kt == qt) {
                int kb = kt * 64;
                int rlo = Q0 + rb + g, rhi = rlo + 8;
#pragma unroll
                for (int nf = 0; nf < 8; nf++) {
                    int k0 = kb + nf * 8 + 2 * t;
                    if (k0     > rlo) S[nf][0] = -INFINITY;
                    if (k0 + 1 > rlo) S[nf][1] = -INFINITY;
                    if (k0     > rhi) S[nf][2] = -INFINITY;
                    if (k0 + 1 > rhi) S[nf][3] = -INFINITY;
                }
            }

            float sc0, sc1;
            {
                float mx0 = -INFINITY, mx1 = -INFINITY;
#pragma unroll
                for (int nf = 0; nf < 8; nf++) {
                    mx0 = fmaxf(mx0, fmaxf(S[nf][0], S[nf][1]));
                    mx1 = fmaxf(mx1, fmaxf(S[nf][2], S[nf][3]));
                }
                mx0 = fmaxf(mx0, __shfl_xor_sync(0xffffffffu, mx0, 1));
                mx0 = fmaxf(mx0, __shfl_xor_sync(0xffffffffu, mx0, 2));
                mx1 = fmaxf(mx1, __shfl_xor_sync(0xffffffffu, mx1, 1));
                mx1 = fmaxf(mx1, __shfl_xor_sync(0xffffffffu, mx1, 2));
                float mn0 = fmaxf(m[0], mx0);
                float mn1 = fmaxf(m[1], mx1);
                sc0 = exp2f(m[0] - mn0);
                sc1 = exp2f(m[1] - mn1);
                m[0] = mn0; m[1] = mn1;
            }

            unsigned E[8][2];
            {
                __half2 hm0 = __float2half2_rn(m[0]);
                __half2 hm1 = __float2half2_rn(m[1]);
#pragma unroll
                for (int nf = 0; nf < 8; nf++) {
                    __half2 p0 = __floats2half2_rn(S[nf][0], S[nf][1]);
                    __half2 p1 = __floats2half2_rn(S[nf][2], S[nf][3]);
                    p0 = __hsub2(p0, hm0);
                    p1 = __hsub2(p1, hm1);
                    E[nf][0] = ex2_f16x2(*(unsigned*)&p0);
                    E[nf][1] = ex2_f16x2(*(unsigned*)&p1);
                }
            }

#pragma unroll
            for (int nf = 0; nf < 9; nf++) {
                O[nf][0] *= sc0; O[nf][1] *= sc0;
                O[nf][2] *= sc1; O[nf][3] *= sc1;
            }

#pragma unroll
            for (int mkey = 0; mkey < 4; mkey++) {
                unsigned a[4];
                a[0] = E[2 * mkey][0];
                a[1] = E[2 * mkey][1];
                a[2] = E[2 * mkey + 1][0];
                a[3] = E[2 * mkey + 1][1];
#pragma unroll
                for (int p = 0; p < 4; p++) {
                    unsigned r0, r1, r2, r3;
                    ldsm4t(r0, r1, r2, r3,
                           vB + (mkey * 16 * F_STR + p * 16) * 2);
                    mma_fp16(O[2 * p],     a, r0, r1);
                    mma_fp16(O[2 * p + 1], a, r2, r3);
                }
                mma_fp16(O[8], a, ONES_H2, ONES_H2);
            }

            // restage kt+2 into this (now fully-read) buffer
            if (kt + 2 <= qt) {
                __syncthreads();   // all warps done reading buf
                fa_stage(K + base + (size_t)(kt + 2) * 64 * HD,
                         V + base + (size_t)(kt + 2) * 64 * HD,
                         sK + buf * FK_B, sV + buf * FK_B, tid);
                CP_COMMIT;
            }
            buf ^= 1;
        }

        // epilogue for this pass
        const float inv0 = 1.f / O[8][0];
        const float inv1 = 1.f / O[8][2];
#pragma unroll
        for (int h2 = 0; h2 < 2; h2++) {
            float inv = h2 ? inv1 : inv0;
            int row = Q0 + rb + g + 8 * h2;
            __half* dst = ctx + ((size_t)(b * SEQ + row)) * DM + hh * HD;
#pragma unroll
            for (int nf = 0; nf < 8; nf++) {
                int c = nf * 8 + 2 * t;
                *(unsigned*)(dst + c) =
                    h2pack(O[nf][2 * h2] * inv, O[nf][2 * h2 + 1] * inv);
            }
        }

        __syncthreads();   // pass-1 readers done before pass-2 restages
    }
}

// ---------------------------------------------------------------------------
// Launch
// ---------------------------------------------------------------------------
extern "C" void kernel_launch(void* const* d_in, const int* in_sizes, int n_in,
                              void* d_out, int out_size)
{
    const float* x  = (const float*)d_in[0];
    const float* wq = (const float*)d_in[1];
    const float* bq = (const float*)d_in[2];
    const float* wk = (const float*)d_in[3];
    const float* bk = (const float*)d_in[4];
    const float* wv = (const float*)d_in[5];
    const float* bv = (const float*)d_in[6];
    const float* wo = (const float*)d_in[7];
    const float* bo = (const float*)d_in[8];
    float* out = (float*)d_out;

    __half *qkv, *ctx, *xh, *wth;
    cudaGetSymbolAddress((void**)&qkv, g_qkv);
    cudaGetSymbolAddress((void**)&ctx, g_ctx);
    cudaGetSymbolAddress((void**)&xh,  g_xh);
    cudaGetSymbolAddress((void**)&wth, g_wth);
    const size_t HSZ = (size_t)BATCH * NH * SEQ * HD;

    cudaFuncSetAttribute(gemm_qkv,
                         cudaFuncAttributeMaxDynamicSharedMemorySize, G_SMEM);
    cudaFuncSetAttribute(gemm_out,
                         cudaFuncAttributeMaxDynamicSharedMemorySize, G_SMEM);
    cudaFuncSetAttribute(flash_fp16,
                         cudaFuncAttributeMaxDynamicSharedMemorySize, FA_SMEM);

    prep_k<<<dim3(32, 32, 5), dim3(32, 8)>>>(x, wq, wk, wv, wo, xh, wth);

    gemm_qkv<<<dim3(DM / 128, MROWS / 128, 3), 256, G_SMEM>>>(
        xh, wth, bq, bk, bv, qkv);

    flash_fp16<<<dim3(NT / 2, BATCH * NH), 128, FA_SMEM>>>(
        qkv, qkv + HSZ, qkv + 2 * HSZ, ctx);

    gemm_out<<<dim3(DM / 128, MROWS / 128), 256, G_SMEM>>>(
        ctx, wth + 3 * (size_t)DM * DM, bo, out);
}